// round 17
// baseline (speedup 1.0000x reference)
#include <cuda_runtime.h>
#include <cuda_bf16.h>
#include <math.h>

#define Nn 2048
#define Dd 512
#define M_LZ 120
#define NB 148              // persistent blocks (1 CTA/SM)
#define NT 512
#define NWARP ((NB * NT) / 32)   // 2368 global warps
#define ELD 132             // eps matrix row stride
#ifndef SIGN_CONV
#define SIGN_CONV (-1.0)
#endif

// ---------------- device scratch (static; no runtime allocation) -------------
__device__ float g_q[Nn];
__device__ float g_deg[Nn];
__device__ __align__(16) float g_V[(M_LZ + 1) * Nn];   // row 0 = ones/sqrt(N)
__device__ __align__(16) float g_LV[(M_LZ + 1) * Nn];  // rows 1..M: L * v_i
__device__ __align__(16) float g_wbuf[2 * Nn];         // ping-pong raw candidates
__device__ __align__(16) float g_ub[Nn];               // ubar = L * w_raw
__device__ float g_c1[M_LZ + 2];         // pass-1 raw dots (LV_i . w_raw)
__device__ float g_gj[M_LZ + 2];         // gram raw dots (w_raw . v_k)
__device__ float g_eps[(M_LZ + 2) * ELD]; // Gram-error matrix
__device__ float g_alpha[M_LZ + 2];      // T diagonal (1-based)
__device__ float g_beta2[M_LZ + 2];      // ||w entering iter j||^2
__device__ float g_b2part[64];           // per-warp ||w||^2 partials
__device__ float g_wspart[64];           // per-warp sum(w) partials
__device__ float g_swupart[NB];          // per-block w.ubar partials
__device__ float g_ssumpart[NB];         // per-block sum(ubar) partials
__device__ float g_mean;
__device__ float g_y[M_LZ];              // tridiagonal eigenvector (fp32)
__device__ __align__(16) float g_fv[Nn];
__device__ __align__(16) float g_z[Nn];
// grid barrier state
__device__ unsigned g_cnt8[8 * 32];      // 8 group counters, 128B apart
__device__ unsigned g_root;
__device__ volatile unsigned g_gen;

// ---------------- reduction helpers ------------------------------------------
__device__ __forceinline__ float warpReduceSumF(float v) {
#pragma unroll
    for (int o = 16; o; o >>= 1) v += __shfl_down_sync(0xffffffffu, v, o);
    return v;
}
__device__ __forceinline__ double warpReduceSumD(double v) {
#pragma unroll
    for (int o = 16; o; o >>= 1) v += __shfl_down_sync(0xffffffffu, v, o);
    return v;
}
__device__ __forceinline__ float blockReduceSumF(float v, float* sh) {
    int lane = threadIdx.x & 31, wid = threadIdx.x >> 5;
    v = warpReduceSumF(v);
    __syncthreads();
    if (lane == 0) sh[wid] = v;
    __syncthreads();
    if (wid == 0) {
        int nw = (blockDim.x + 31) >> 5;
        float s = (lane < nw) ? sh[lane] : 0.f;
        s = warpReduceSumF(s);
        if (lane == 0) sh[0] = s;
    }
    __syncthreads();
    return sh[0];
}

__device__ __forceinline__ float sigmoidf_(float s) {
    if (s >= 0.f) { float ez = __expf(-s); return 1.f / (1.f + ez); }
    float ez = __expf(s); return ez / (1.f + ez);
}

// ---------------- acq_rel grid barrier (two-level tree) -----------------------
__device__ __forceinline__ unsigned atom_add_acqrel(unsigned* p, unsigned v) {
    unsigned old;
    asm volatile("atom.acq_rel.gpu.global.add.u32 %0, [%1], %2;"
                 : "=r"(old) : "l"(p), "r"(v) : "memory");
    return old;
}
__device__ __forceinline__ void st_release_u32(volatile unsigned* p, unsigned v) {
    asm volatile("st.release.gpu.global.u32 [%0], %1;" :: "l"(p), "r"(v) : "memory");
}
__device__ __forceinline__ unsigned ld_acquire_u32(volatile unsigned* p) {
    unsigned v;
    asm volatile("ld.acquire.gpu.global.u32 %0, [%1];" : "=r"(v) : "l"(p) : "memory");
    return v;
}
__device__ __forceinline__ void gbar() {
    __syncthreads();
    if (threadIdx.x == 0) {
        unsigned gen = *(volatile unsigned*)&g_gen;
        int grp = blockIdx.x & 7;
        unsigned gsz = (unsigned)(NB >> 3) + ((unsigned)grp < (unsigned)(NB & 7) ? 1u : 0u);
        bool rel = false;
        if (atom_add_acqrel(&g_cnt8[grp * 32], 1u) == gsz - 1u) {
            g_cnt8[grp * 32] = 0;
            if (atom_add_acqrel(&g_root, 1u) == 7u) {
                g_root = 0;
                st_release_u32(&g_gen, gen + 1);
                rel = true;
            }
        }
        if (!rel) {
            while (ld_acquire_u32(&g_gen) == gen) __nanosleep(16);
        }
    }
    __syncthreads();
}

// ---------------- q_i = sum_k w_k x_ik^2 -------------------------------------
__global__ void k_q(const float* __restrict__ x, const float* __restrict__ w) {
    __shared__ float sh[4];
    int i = blockIdx.x, tid = threadIdx.x;
    float acc = 0.f;
    for (int k = tid; k < Dd; k += 128) {
        float xv = x[(size_t)i * Dd + k];
        acc = fmaf(w[k] * xv, xv, acc);
    }
    acc = blockReduceSumF(acc, sh);
    if (tid == 0) g_q[i] = acc;
}

// ---------------- G = sigmoid(q_i + q_j - 2*X diag(w) X^T + b) ---------------
__global__ void k_gemm(const float* __restrict__ x, const float* __restrict__ w,
                       const float* __restrict__ bptr, float* __restrict__ G) {
    __shared__ float As[16][132];
    __shared__ float Bs[16][132];
    int bm = blockIdx.y * 128, bn = blockIdx.x * 128;
    int tid = threadIdx.x;
    int tx = tid & 15, ty = tid >> 4;
    float acc[8][8];
#pragma unroll
    for (int i = 0; i < 8; i++)
#pragma unroll
        for (int j = 0; j < 8; j++) acc[i][j] = 0.f;

    for (int k0 = 0; k0 < Dd; k0 += 16) {
#pragma unroll
        for (int s = 0; s < 8; s++) {
            int li = tid + s * 256;
            int r = li >> 4, kk = li & 15;
            As[kk][r] = x[(size_t)(bm + r) * Dd + k0 + kk] * w[k0 + kk];
            Bs[kk][r] = x[(size_t)(bn + r) * Dd + k0 + kk];
        }
        __syncthreads();
#pragma unroll
        for (int kk = 0; kk < 16; kk++) {
            float a[8], bb[8];
#pragma unroll
            for (int i = 0; i < 8; i++) a[i] = As[kk][ty * 8 + i];
#pragma unroll
            for (int j = 0; j < 8; j++) bb[j] = Bs[kk][tx * 8 + j];
#pragma unroll
            for (int i = 0; i < 8; i++)
#pragma unroll
                for (int j = 0; j < 8; j++) acc[i][j] = fmaf(a[i], bb[j], acc[i][j]);
        }
        __syncthreads();
    }
    float bv = bptr[0];
#pragma unroll
    for (int i = 0; i < 8; i++) {
        int row = bm + ty * 8 + i;
        float qi = g_q[row] + bv;
#pragma unroll
        for (int j = 0; j < 8; j += 4) {
            int col = bn + tx * 8 + j;
            float4 o;
            o.x = sigmoidf_(qi + g_q[col + 0] - 2.f * acc[i][j + 0]);
            o.y = sigmoidf_(qi + g_q[col + 1] - 2.f * acc[i][j + 1]);
            o.z = sigmoidf_(qi + g_q[col + 2] - 2.f * acc[i][j + 2]);
            o.w = sigmoidf_(qi + g_q[col + 3] - 2.f * acc[i][j + 3]);
            *reinterpret_cast<float4*>(&G[(size_t)row * Nn + col]) = o;
        }
    }
}

// ---------------- persistent Lanczos + fused tail -----------------------------
__global__ void __launch_bounds__(NT) k_lanczos(const float* __restrict__ G,
                                                float* __restrict__ out) {
    const int tid = threadIdx.x;
    const int bid = blockIdx.x;
    const int gid = bid * NT + tid;
    const int gw = gid >> 5, lane = gid & 31;
    const int wib = tid >> 5;              // warp in block (0..15)
    const int stripe = gid >> 11;          // 0..36
    const int selem = gid & (Nn - 1);
    const float c0 = rsqrtf((float)Nn);

    __shared__ alignas(16) float s_w[Nn];  // staged vector (8KB) — float4-accessed
    __shared__ float s_wu16[16], s_sum16[16];
    __shared__ float s_scal[3];            // swu, ssum, wsum totals
    __shared__ float s_c1n[M_LZ + 2];
    __shared__ float s_epsj[M_LZ + 2];
    __shared__ float s_coef[M_LZ + 2];
    float4* s_w4 = reinterpret_cast<float4*>(s_w);

    // ---- init: V0 = ones*c0, eps00 = 0, deg = rowsum, v1 = hash - mean -------
    float r = 0.f;
    if (gid < Nn) {
        unsigned u = (unsigned)(gid + 1) * 2654435761u;
        u ^= u >> 16; u *= 2246822519u; u ^= u >> 13; u *= 3266489917u; u ^= u >> 16;
        r = (float)(u & 0xFFFFFFu) * (1.f / 16777216.f) - 0.5f;
        g_V[gid] = c0;
    }
    if (gid == 0) { g_mean = 0.f; g_eps[0] = 0.f; }
    if (gw < Nn) {      // degree: one warp per row
        const float4* Gr = reinterpret_cast<const float4*>(G + (size_t)gw * Nn);
        float acc = 0.f;
#pragma unroll 8
        for (int t = lane; t < Nn / 4; t += 32) {
            float4 a = Gr[t];
            acc += a.x + a.y + a.z + a.w;
        }
        acc = warpReduceSumF(acc);
        if (lane == 0) g_deg[gw] = acc;
    }
    gbar();
    if (gw < Nn / 32) {
        float s = warpReduceSumF(r);
        if (lane == 0) atomicAdd(&g_mean, s);
    }
    gbar();
    if (gid < Nn) g_wbuf[Nn + gid] = r - g_mean * (1.f / (float)Nn);  // W[1]
    gbar();

    for (int j = 1; j <= M_LZ; j++) {
        const float* Wcur = g_wbuf + (size_t)(j & 1) * Nn;
        float* Wnxt = g_wbuf + (size_t)((j + 1) & 1) * Nn;

        // ==== Phase A: stage w; partials; clear Wnxt; dots1; gram; matvec ====
        s_w4[tid] = reinterpret_cast<const float4*>(Wcur)[tid];
        __syncthreads();
        if (gid < Nn) {
            float wv = s_w[gid];
            float p = warpReduceSumF(wv * wv);
            float q = warpReduceSumF(wv);
            if (lane == 0) { g_b2part[gw] = p; g_wspart[gw] = q; }
            Wnxt[gid] = 0.f;
        }
        {
            float lwu = 0.f, lsum = 0.f;
            const int nd = j - 1;
            if (gw < nd) {
                // dots1: c1[i] = LV[i] . w_raw
                int i = 1 + gw;
                const float4* lv = reinterpret_cast<const float4*>(g_LV + (size_t)i * Nn);
                float acc = 0.f;
#pragma unroll 8
                for (int t = lane; t < Nn / 4; t += 32) {
                    float4 a = lv[t], bq = s_w4[t];
                    acc += a.x * bq.x + a.y * bq.y + a.z * bq.z + a.w * bq.w;
                }
                acc = warpReduceSumF(acc);
                if (lane == 0) g_c1[i] = acc;
            } else if (gw < 2 * nd) {
                // gram: gj[k] = w_raw . v_k
                int k = 1 + (gw - nd);
                const float4* vk = reinterpret_cast<const float4*>(g_V + (size_t)k * Nn);
                float acc = 0.f;
#pragma unroll 8
                for (int t = lane; t < Nn / 4; t += 32) {
                    float4 a = vk[t], bq = s_w4[t];
                    acc += a.x * bq.x + a.y * bq.y + a.z * bq.z + a.w * bq.w;
                }
                acc = warpReduceSumF(acc);
                if (lane == 0) g_gj[k] = acc;
            } else {
                int row = gw - 2 * nd;
                if (row < Nn) {
                    const float4* Gr = reinterpret_cast<const float4*>(G + (size_t)row * Nn);
                    float acc = 0.f;
#pragma unroll 8
                    for (int t = lane; t < Nn / 4; t += 32) {
                        float4 a = Gr[t], bq = s_w4[t];
                        acc += a.x * bq.x + a.y * bq.y + a.z * bq.z + a.w * bq.w;
                    }
                    acc = warpReduceSumF(acc);
                    if (lane == 0) {
                        float ub = g_deg[row] * s_w[row] - acc;
                        g_ub[row] = ub;
                        lwu = s_w[row] * ub;
                        lsum = ub;
                    }
                }
            }
            if (lane == 0) { s_wu16[wib] = lwu; s_sum16[wib] = lsum; }
        }
        __syncthreads();
        if (tid == 0) {
            float a0 = 0.f, a1 = 0.f;
#pragma unroll
            for (int k = 0; k < 16; k++) { a0 += s_wu16[k]; a1 += s_sum16[k]; }
            g_swupart[bid] = a0;
            g_ssumpart[bid] = a1;
        }
        gbar();

        // ==== Phase B: scalars; c1n/epsj; c2 = -eps*c1n; combined subtraction =
        float b2l = g_b2part[lane] + g_b2part[lane + 32];
        b2l = warpReduceSumF(b2l);
        float b2 = __shfl_sync(0xffffffffu, b2l, 0);
        float invb = rsqrtf(fmaxf(b2, 1e-30f));
        if (wib == 0) {
            float swl = 0.f, ssl = 0.f;
            for (int k = lane; k < NB; k += 32) { swl += g_swupart[k]; ssl += g_ssumpart[k]; }
            float wsl = g_wspart[lane] + g_wspart[lane + 32];
            swl = warpReduceSumF(swl);
            ssl = warpReduceSumF(ssl);
            wsl = warpReduceSumF(wsl);
            if (lane == 0) { s_scal[0] = swl; s_scal[1] = ssl; s_scal[2] = wsl; }
        }
        __syncthreads();
        if (tid <= j) {
            int i = tid;
            float c1n, ej;
            if (i == 0)      { c1n = c0 * s_scal[1] * invb; ej = c0 * s_scal[2] * invb; }
            else if (i == j) { c1n = s_scal[0] * invb * invb; ej = b2 * invb * invb - 1.f; }
            else             { c1n = g_c1[i] * invb; ej = g_gj[i] * invb; }
            s_c1n[i] = c1n;
            s_epsj[i] = ej;
        }
        __syncthreads();
        for (int i = wib; i <= j; i += 16) {
            float acc = 0.f;
            if (i == j) {
                for (int k = lane; k <= j; k += 32) acc += s_c1n[k] * s_epsj[k];
            } else {
                const float* er = g_eps + (size_t)i * ELD;
                for (int k = lane; k <= j; k += 32) {
                    float e = (k == j) ? s_epsj[i] : er[k];
                    acc += s_c1n[k] * e;
                }
            }
            acc = warpReduceSumF(acc);
            if (lane == 0) s_coef[i] = s_c1n[i] - acc;   // c1n_i + c2_i
        }
        __syncthreads();
        if (bid == 0 && tid <= j) {                      // commit eps row/col j
            g_eps[(size_t)j * ELD + tid] = s_epsj[tid];
            g_eps[(size_t)tid * ELD + j] = s_epsj[tid];
        }
        if (stripe < 32 && (stripe == 0 || stripe < j)) {
            int t = selem;
            float part = 0.f;
#pragma unroll 4
            for (int i = stripe; i < j; i += 32)
                part = fmaf(s_coef[i], g_V[(size_t)i * Nn + t], part);
            if (stripe == 0) {
                float wv = s_w[t];
                float vj = wv * invb;
                float uv = g_ub[t] * invb;
                g_V[(size_t)j * Nn + t] = vj;
                g_LV[(size_t)j * Nn + t] = uv;
                part = fmaf(s_coef[j], vj, part) - uv;   // include i=j term; seed u
            }
            atomicAdd(&Wnxt[t], -part);
        }
        if (gid == 0) { g_beta2[j] = b2; g_alpha[j] = s_coef[j]; }
        gbar();
    }

    // ==== Fused tail 1: tridiag smallest eigenpair (block 0, warp 0) =========
    {
        __shared__ float aa[M_LZ], bb2s[M_LZ], bbs[M_LZ];
        __shared__ float dw[M_LZ], ew[M_LZ], fw[M_LZ], yv[M_LZ], rv[M_LZ];
        __shared__ float sx[32];
        __shared__ int scnt[32];
        __shared__ float slo, shi;
        if (bid == 0 && wib == 0) {
            int ln = lane;
            for (int i = ln; i < M_LZ; i += 32) {
                aa[i] = g_alpha[i + 1];
                float b2 = (i < M_LZ - 1) ? g_beta2[i + 2] : 0.f;
                bb2s[i] = b2;
                bbs[i] = sqrtf(b2);
            }
            __syncwarp();
            if (ln == 0) {
                float lo = 3.4e38f, hi = -3.4e38f;
                for (int i = 0; i < M_LZ; i++) {
                    float bl = (i > 0) ? bbs[i - 1] : 0.f;
                    float br = (i < M_LZ - 1) ? bbs[i] : 0.f;
                    lo = fminf(lo, aa[i] - bl - br);
                    hi = fmaxf(hi, aa[i] + bl + br);
                }
                slo = lo - 1.f; shi = hi + 1.f;
            }
            __syncwarp();
            for (int round = 0; round < 5; round++) {
                float lo = slo, hi = shi;
                float x = lo + (hi - lo) * (float)(ln + 1) * (1.f / 33.f);
                float d = aa[0] - x;
                int cnt = (d < 0.f);
                for (int i = 1; i < M_LZ; i++) {
                    if (fabsf(d) < 1e-20f) d = (d < 0.f ? -1e-20f : 1e-20f);
                    d = aa[i] - x - __fdividef(bb2s[i - 1], d);
                    cnt += (d < 0.f);
                }
                sx[ln] = x; scnt[ln] = cnt;
                __syncwarp();
                if (ln == 0) {
                    float nlo = lo, nhi = hi;
                    int k = 0;
                    while (k < 32 && scnt[k] < 1) k++;
                    if (k < 32) { nhi = sx[k]; if (k > 0) nlo = sx[k - 1]; }
                    else        { nlo = sx[31]; }
                    slo = nlo; shi = nhi;
                }
                __syncwarp();
            }
            float th = 0.5f * (slo + shi);
            if (ln == 0) {
                for (int i = 0; i < M_LZ; i++) rv[i] = 1.f;
                for (int it = 0; it < 2; it++) {
                    for (int i = 0; i < M_LZ; i++) {
                        dw[i] = aa[i] - th;
                        ew[i] = (i < M_LZ - 1) ? bbs[i] : 0.f;
                        fw[i] = 0.f;
                        yv[i] = rv[i];
                    }
                    for (int i = 0; i < M_LZ - 1; i++) {
                        float s = bbs[i];
                        if (fabsf(s) > fabsf(dw[i])) {
                            float od = dw[i], oe = ew[i], of = fw[i];
                            dw[i] = s;       ew[i] = dw[i + 1]; fw[i] = ew[i + 1];
                            s = od;          dw[i + 1] = oe;    ew[i + 1] = of;
                            float ry = yv[i]; yv[i] = yv[i + 1]; yv[i + 1] = ry;
                        }
                        float p = dw[i];
                        if (fabsf(p) < 1e-20f) { p = (p < 0.f ? -1e-20f : 1e-20f); dw[i] = p; }
                        float m = __fdividef(s, p);
                        dw[i + 1] -= m * ew[i];
                        ew[i + 1] -= m * fw[i];
                        yv[i + 1] -= m * yv[i];
                    }
                    for (int i = M_LZ - 1; i >= 0; i--) {
                        float v = yv[i];
                        if (i + 1 < M_LZ) v -= ew[i] * yv[i + 1];
                        if (i + 2 < M_LZ) v -= fw[i] * yv[i + 2];
                        float p = dw[i];
                        if (fabsf(p) < 1e-20f) p = (p < 0.f ? -1e-20f : 1e-20f);
                        yv[i] = __fdividef(v, p);
                    }
                    float n2 = 0.f;
                    for (int i = 0; i < M_LZ; i++) n2 += yv[i] * yv[i];
                    float inv = rsqrtf(fmaxf(n2, 1e-30f));
                    for (int i = 0; i < M_LZ; i++) rv[i] = yv[i] * inv;
                }
                for (int i = 0; i < M_LZ; i++) g_y[i] = rv[i];
            }
        }
    }
    gbar();

    // ==== Fused tail 2: fv[t] = sum_r y_{r-1} V[r][t]  (warp per element) ====
    if (gw < Nn) {
        float acc = 0.f;
        for (int rr = 1 + lane; rr <= M_LZ; rr += 32)
            acc = fmaf(g_y[rr - 1], g_V[(size_t)rr * Nn + gw], acc);
        acc = warpReduceSumF(acc);
        if (lane == 0) g_fv[gw] = acc;
    }
    gbar();

    // ==== Fused tail 3: z = L * fv (warp per row, staged fv) =================
    s_w4[tid] = reinterpret_cast<const float4*>(g_fv)[tid];
    __syncthreads();
    if (gw < Nn) {
        const float4* Gr = reinterpret_cast<const float4*>(G + (size_t)gw * Nn);
        float acc = 0.f;
#pragma unroll 8
        for (int t = lane; t < Nn / 4; t += 32) {
            float4 a = Gr[t], bq = s_w4[t];
            acc += a.x * bq.x + a.y * bq.y + a.z * bq.z + a.w * bq.w;
        }
        acc = warpReduceSumF(acc);
        if (lane == 0) g_z[gw] = g_deg[gw] * s_w[gw] - acc;
    }
    gbar();

    // ==== Fused tail 4: Rayleigh quotient + sign + write (block 0) ===========
    if (bid == 0) {
        __shared__ double shd[16];
        __shared__ float sabs[16];
        __shared__ int sidx[16];
        __shared__ double ssign;
        double num = 0.0, den = 0.0;
        float bav = -1.f; int bix = 0;
        float av[4];
#pragma unroll
        for (int k = 0; k < 4; k++) {
            int t = tid + k * NT;
            float a = g_fv[t];
            av[k] = a;
            num += (double)a * (double)g_z[t];
            den += (double)a * (double)a;
            float fa = fabsf(a);
            if (fa > bav || (fa == bav && t < bix)) { bav = fa; bix = t; }
        }
        // block reduce num
        {
            double v = warpReduceSumD(num);
            if ((tid & 31) == 0) shd[tid >> 5] = v;
            __syncthreads();
            if (tid < 16) {
                double s = shd[tid];
                s += __shfl_down_sync(0xffffu, s, 8);
                s += __shfl_down_sync(0xffffu, s, 4);
                s += __shfl_down_sync(0xffffu, s, 2);
                s += __shfl_down_sync(0xffffu, s, 1);
                if (tid == 0) shd[0] = s;
            }
            __syncthreads();
            num = shd[0];
            __syncthreads();
        }
        // block reduce den
        {
            double v = warpReduceSumD(den);
            if ((tid & 31) == 0) shd[tid >> 5] = v;
            __syncthreads();
            if (tid < 16) {
                double s = shd[tid];
                s += __shfl_down_sync(0xffffu, s, 8);
                s += __shfl_down_sync(0xffffu, s, 4);
                s += __shfl_down_sync(0xffffu, s, 2);
                s += __shfl_down_sync(0xffffu, s, 1);
                if (tid == 0) shd[0] = s;
            }
            __syncthreads();
            den = shd[0];
            __syncthreads();
        }
        // argmax |fv|
#pragma unroll
        for (int o = 16; o; o >>= 1) {
            float ov = __shfl_down_sync(0xffffffffu, bav, o);
            int   oi = __shfl_down_sync(0xffffffffu, bix, o);
            if (ov > bav || (ov == bav && oi < bix)) { bav = ov; bix = oi; }
        }
        if ((tid & 31) == 0) { sabs[tid >> 5] = bav; sidx[tid >> 5] = bix; }
        __syncthreads();
        if (tid == 0) {
            float bv = sabs[0]; int bi = sidx[0];
            for (int i = 1; i < 16; i++)
                if (sabs[i] > bv || (sabs[i] == bv && sidx[i] < bi)) { bv = sabs[i]; bi = sidx[i]; }
            ssign = (g_fv[bi] >= 0.f ? 1.0 : -1.0) * SIGN_CONV;
            out[(size_t)Nn * Nn] = (float)(num / fmax(den, 1e-300));
        }
        __syncthreads();
        double sc = ssign / sqrt(fmax(den, 1e-300));
        size_t base = (size_t)Nn * Nn + 1;
#pragma unroll
        for (int k = 0; k < 4; k++) {
            int t = tid + k * NT;
            out[base + t] = (float)((double)av[k] * sc);
        }
    }
}

// ---------------- launcher ----------------------------------------------------
extern "C" void kernel_launch(void* const* d_in, const int* in_sizes, int n_in,
                              void* d_out, int out_size) {
    const float* x = (const float*)d_in[0];
    const float* w = (const float*)d_in[1];
    const float* b = (const float*)d_in[2];
    float* out = (float*)d_out;
    float* G = out;   // grouping matrix lives at the front of d_out

    k_q<<<Nn, 128>>>(x, w);
    k_gemm<<<dim3(Nn / 128, Nn / 128), 256>>>(x, w, b, G);
    k_lanczos<<<NB, NT>>>(G, out);
}